// round 15
// baseline (speedup 1.0000x reference)
#include <cuda_runtime.h>
#include <math.h>

#define N_NODES   50000
#define N_HE      20000
#define N_PAIRS   400000
#define E_EDGES   800000
#define E2        (E_EDGES + N_NODES)
#define L_EDGES   100000

// ---------------- scratch (device globals; no runtime allocation) ----------------
__device__ float g_h0[N_NODES * 256];   // hconv: m128 staging
__device__ float g_m [N_HE    * 256];   // hyperedge messages post-GEMM
__device__ float g_h1[N_NODES * 256];   // activations
__device__ float g_hg[N_NODES * 256];   // GEMM output features
__device__ float g_as[N_NODES];
__device__ float g_ad[N_NODES];
__device__ float g_z [N_NODES * 64];

// CSR: single backing array for counts (one memset)
__device__ int c_cnt[N_HE + N_NODES + N_NODES];
#define c_cnt_he (c_cnt)
#define c_cnt_nd (c_cnt + N_HE)
#define c_cnt_g  (c_cnt + N_HE + N_NODES)
__device__ int c_off_he[N_HE],    c_cur_he[N_HE],    c_val_he[N_PAIRS];
__device__ int c_off_nd[N_NODES], c_cur_nd[N_NODES], c_val_nd[N_PAIRS];
__device__ int c_off_g [N_NODES], c_cur_g [N_NODES], c_val_g [E2];

typedef unsigned long long u64;

__device__ __forceinline__ float lrelu02(float x) { return x > 0.f ? x : 0.2f * x; }
__device__ __forceinline__ void f4add(float4& a, const float4 b) {
    a.x += b.x; a.y += b.y; a.z += b.z; a.w += b.w;
}
__device__ __forceinline__ void f4fma(float4& a, float w, const float4 b) {
    a.x = fmaf(w, b.x, a.x); a.y = fmaf(w, b.y, a.y);
    a.z = fmaf(w, b.z, a.z); a.w = fmaf(w, b.w, a.w);
}
// ---- packed fp32x2 (Blackwell FFMA2) ----
__device__ __forceinline__ u64 pk2(float lo, float hi) {
    u64 r; asm("mov.b64 %0, {%1, %2};" : "=l"(r) : "f"(lo), "f"(hi)); return r;
}
__device__ __forceinline__ u64 dup2(float x) { return pk2(x, x); }
__device__ __forceinline__ void unpk2(float& lo, float& hi, u64 v) {
    asm("mov.b64 {%0, %1}, %2;" : "=f"(lo), "=f"(hi) : "l"(v));
}
__device__ __forceinline__ void fma2(u64& d, u64 a, u64 b) {
    asm("fma.rn.f32x2 %0, %1, %2, %0;" : "+l"(d) : "l"(a), "l"(b));
}

// ---------------- GEMM: C[M,N] = A[M,K] @ B[K,N], fp32, f32x2 core, double-buffered.
// EPI: fused C = relu(C + bias[col]).
// DOTS: (requires BN==N, grid.x==1) also writes row dots with av_s/av_d to dot_s/dot_d.
template<int BM, int BN, int BK, int TM, int TN, bool EPI, bool DOTS>
__global__ void __launch_bounds__((BM / TM) * (BN / TN))
sgemm(const float* __restrict__ A, const float* __restrict__ B, float* __restrict__ C,
      int M, int N, int K, const float* __restrict__ bias,
      const float* __restrict__ av_s, const float* __restrict__ av_d,
      float* __restrict__ dot_s, float* __restrict__ dot_d) {
    constexpr int NT = (BM / TM) * (BN / TN);
    constexpr int LA = BM * BK / 4 / NT;
    constexpr int LB = BK * BN / 4 / NT;
    __shared__ float As[2][BK][BM + 4];
    __shared__ float Bs[2][BK][BN];
    const int tid = threadIdx.x;
    const int tx = tid % (BN / TN);
    const int ty = tid / (BN / TN);
    const int rowBase = blockIdx.y * BM, colBase = blockIdx.x * BN;
    float4 ra[LA], rb[LB];

    auto loadA = [&](int k0) {
        #pragma unroll
        for (int s = 0; s < LA; s++) {
            int f = tid + s * NT;
            int r = f / (BK / 4), c = (f % (BK / 4)) * 4;
            int gr = rowBase + r;
            ra[s] = (gr < M) ? *(const float4*)&A[(size_t)gr * K + k0 + c]
                             : make_float4(0.f, 0.f, 0.f, 0.f);
        }
    };
    auto loadB = [&](int k0) {
        #pragma unroll
        for (int s = 0; s < LB; s++) {
            int f = tid + s * NT;
            int r = f / (BN / 4), c = (f % (BN / 4)) * 4;
            rb[s] = *(const float4*)&B[(size_t)(k0 + r) * N + colBase + c];
        }
    };
    auto stA = [&](int buf) {
        #pragma unroll
        for (int s = 0; s < LA; s++) {
            int f = tid + s * NT;
            int r = f / (BK / 4), c = (f % (BK / 4)) * 4;
            As[buf][c + 0][r] = ra[s].x; As[buf][c + 1][r] = ra[s].y;
            As[buf][c + 2][r] = ra[s].z; As[buf][c + 3][r] = ra[s].w;
        }
    };
    auto stB = [&](int buf) {
        #pragma unroll
        for (int s = 0; s < LB; s++) {
            int f = tid + s * NT;
            int r = f / (BN / 4), c = (f % (BN / 4)) * 4;
            *(float4*)&Bs[buf][r][c] = rb[s];
        }
    };

    u64 acc[TM][TN / 2];
    #pragma unroll
    for (int i = 0; i < TM; i++)
        #pragma unroll
        for (int j = 0; j < TN / 2; j++) acc[i][j] = 0ULL;

    loadA(0); loadB(0); stA(0); stB(0);
    __syncthreads();
    const int T = K / BK;
    int cur = 0;
    for (int t = 0; t < T; t++) {
        if (t + 1 < T) { loadA((t + 1) * BK); loadB((t + 1) * BK); }
        #pragma unroll
        for (int k = 0; k < BK; k++) {
            float af[TM], bf[TN];
            #pragma unroll
            for (int i = 0; i < TM; i += 4)
                *(float4*)&af[i] = *(const float4*)&As[cur][k][ty * TM + i];
            #pragma unroll
            for (int j = 0; j < TN; j += 4)
                *(float4*)&bf[j] = *(const float4*)&Bs[cur][k][tx * TN + j];
            u64 a2[TM], b2[TN / 2];
            #pragma unroll
            for (int i = 0; i < TM; i++) a2[i] = dup2(af[i]);
            #pragma unroll
            for (int j = 0; j < TN / 2; j++) b2[j] = pk2(bf[2 * j], bf[2 * j + 1]);
            #pragma unroll
            for (int i = 0; i < TM; i++)
                #pragma unroll
                for (int j = 0; j < TN / 2; j++) fma2(acc[i][j], a2[i], b2[j]);
        }
        if (t + 1 < T) {
            stA(cur ^ 1); stB(cur ^ 1);
            __syncthreads();
            cur ^= 1;
        }
    }
    float bb[TN];
    if constexpr (EPI) {
        #pragma unroll
        for (int j = 0; j < TN; j++) bb[j] = __ldg(&bias[colBase + tx * TN + j]);
    }
    float avs[TN], avd[TN];
    if constexpr (DOTS) {
        #pragma unroll
        for (int j = 0; j < TN; j++) {
            avs[j] = __ldg(&av_s[tx * TN + j]);
            avd[j] = __ldg(&av_d[tx * TN + j]);
        }
    }
    #pragma unroll
    for (int i = 0; i < TM; i++) {
        int gr = rowBase + ty * TM + i;
        float vbuf[TN];
        #pragma unroll
        for (int j = 0; j < TN / 2; j++) unpk2(vbuf[2 * j], vbuf[2 * j + 1], acc[i][j]);
        if constexpr (EPI) {
            #pragma unroll
            for (int j = 0; j < TN; j++) vbuf[j] = fmaxf(vbuf[j] + bb[j], 0.f);
        }
        if (gr < M) {
            #pragma unroll
            for (int j = 0; j < TN / 4; j++)
                *(float4*)&C[(size_t)gr * N + colBase + tx * TN + 4 * j] =
                    make_float4(vbuf[4 * j], vbuf[4 * j + 1], vbuf[4 * j + 2], vbuf[4 * j + 3]);
        }
        if constexpr (DOTS) {
            float ps = 0.f, pd = 0.f;
            #pragma unroll
            for (int j = 0; j < TN; j++) {
                ps = fmaf(vbuf[j], avs[j], ps);
                pd = fmaf(vbuf[j], avd[j], pd);
            }
            #pragma unroll
            for (int off = 8; off; off >>= 1) {
                ps += __shfl_xor_sync(0xffffffffu, ps, off);
                pd += __shfl_xor_sync(0xffffffffu, pd, off);
            }
            if (tx == 0 && gr < M) { dot_s[gr] = ps; dot_d[gr] = pd; }
        }
    }
}

// ---------------- fused decode: gather -> L1 -> L2 -> L3 -> final + argmax ---------
#define DEC_RS 132   // sAct row stride (BM + 4)
#define DEC_SMEM ((2 * 16 * DEC_RS + 2 * 16 * 64 + 64 * 64 * 2 + 2 * 64 * DEC_RS) * 4)
__global__ void __launch_bounds__(256)
k_decode(const float* __restrict__ Z,
         const float* __restrict__ Wm1, const float* __restrict__ bm1,
         const float* __restrict__ Wm2, const float* __restrict__ bm2,
         const float* __restrict__ Wm3, const float* __restrict__ bm3,
         const float* __restrict__ Wm4, const float* __restrict__ bm4,
         const int* __restrict__ gidx, float* __restrict__ outF) {
    constexpr int BM = 128, BN = 64, BK = 16, TM = 8, TN = 4, NT = 256;
    extern __shared__ float smx[];
    float* As_ = smx;                      // [2][BK][DEC_RS]
    float* Bs_ = As_ + 2 * BK * DEC_RS;    // [2][BK][BN]
    float* sW2 = Bs_ + 2 * BK * BN;        // [64][64]
    float* sW3 = sW2 + 64 * 64;
    float* sA0 = sW3 + 64 * 64;            // [64][DEC_RS]  act (transposed: [k][row])
    float* sA1 = sA0 + 64 * DEC_RS;
    const int tid = threadIdx.x;
    const int tx = tid & 15, ty = tid >> 4;
    const int rowBase = blockIdx.x * BM;
    const int M = L_EDGES;

    // stage W2/W3
    #pragma unroll
    for (int i = tid; i < 64 * 64 / 4; i += NT) {
        ((float4*)sW2)[i] = __ldg((const float4*)Wm2 + i);
        ((float4*)sW3)[i] = __ldg((const float4*)Wm3 + i);
    }

    // ---- L1: act = relu(concat(z[src],z[dst]) @ Wm1 + bm1), K=128, streamed ----
    float4 ra[2], rb;
    auto loadA = [&](int k0) {
        #pragma unroll
        for (int s = 0; s < 2; s++) {
            int f = tid + s * NT;
            int r = f >> 2, c = (f & 3) * 4;
            int gr = rowBase + r;
            if (gr < M) {
                int col = k0 + c;
                int node = (col < 64) ? __ldg(&gidx[gr]) : __ldg(&gidx[M + gr]);
                ra[s] = *(const float4*)&Z[(size_t)node * 64 + (col & 63)];
            } else ra[s] = make_float4(0.f, 0.f, 0.f, 0.f);
        }
    };
    auto loadB = [&](int k0) {
        int r = tid >> 4, c = (tid & 15) * 4;
        rb = *(const float4*)&Wm1[(size_t)(k0 + r) * 64 + c];
    };
    auto stA = [&](int buf) {
        float* p = As_ + buf * (BK * DEC_RS);
        #pragma unroll
        for (int s = 0; s < 2; s++) {
            int f = tid + s * NT;
            int r = f >> 2, c = (f & 3) * 4;
            p[(c + 0) * DEC_RS + r] = ra[s].x; p[(c + 1) * DEC_RS + r] = ra[s].y;
            p[(c + 2) * DEC_RS + r] = ra[s].z; p[(c + 3) * DEC_RS + r] = ra[s].w;
        }
    };
    auto stB = [&](int buf) {
        int r = tid >> 4, c = (tid & 15) * 4;
        *(float4*)&Bs_[buf * (BK * BN) + r * BN + c] = rb;
    };

    u64 acc[TM][TN / 2];
    #pragma unroll
    for (int i = 0; i < TM; i++) { acc[i][0] = 0ULL; acc[i][1] = 0ULL; }
    loadA(0); loadB(0); stA(0); stB(0);
    __syncthreads();
    int cur = 0;
    for (int t = 0; t < 8; t++) {
        if (t + 1 < 8) { loadA((t + 1) * BK); loadB((t + 1) * BK); }
        const float* pa = As_ + cur * (BK * DEC_RS);
        const float* pb = Bs_ + cur * (BK * BN);
        #pragma unroll
        for (int k = 0; k < BK; k++) {
            float af[TM], bf[TN];
            *(float4*)&af[0] = *(const float4*)&pa[k * DEC_RS + ty * TM];
            *(float4*)&af[4] = *(const float4*)&pa[k * DEC_RS + ty * TM + 4];
            *(float4*)&bf[0] = *(const float4*)&pb[k * BN + tx * TN];
            u64 a2[TM], b2[2];
            #pragma unroll
            for (int i = 0; i < TM; i++) a2[i] = dup2(af[i]);
            b2[0] = pk2(bf[0], bf[1]); b2[1] = pk2(bf[2], bf[3]);
            #pragma unroll
            for (int i = 0; i < TM; i++) { fma2(acc[i][0], a2[i], b2[0]); fma2(acc[i][1], a2[i], b2[1]); }
        }
        if (t + 1 < 8) { stA(cur ^ 1); stB(cur ^ 1); __syncthreads(); cur ^= 1; }
    }

    // store act1 transposed into sA0 with relu+bias
    {
        float vb[TM][TN];
        float bbl[TN];
        #pragma unroll
        for (int j = 0; j < TN; j++) bbl[j] = __ldg(&bm1[tx * TN + j]);
        #pragma unroll
        for (int i = 0; i < TM; i++) {
            unpk2(vb[i][0], vb[i][1], acc[i][0]);
            unpk2(vb[i][2], vb[i][3], acc[i][1]);
            #pragma unroll
            for (int j = 0; j < TN; j++) vb[i][j] = fmaxf(vb[i][j] + bbl[j], 0.f);
        }
        #pragma unroll
        for (int j = 0; j < TN; j++) {
            int col = tx * TN + j;
            *(float4*)&sA0[col * DEC_RS + ty * TM] =
                make_float4(vb[0][j], vb[1][j], vb[2][j], vb[3][j]);
            *(float4*)&sA0[col * DEC_RS + ty * TM + 4] =
                make_float4(vb[4][j], vb[5][j], vb[6][j], vb[7][j]);
        }
    }
    __syncthreads();

    // ---- generic smem layer: act_out = relu(act_in @ W + b), K=N=64 ----
    auto layer = [&](const float* actIn, const float* W, const float* bl, float* actOut) {
        u64 a_[TM][2];
        #pragma unroll
        for (int i = 0; i < TM; i++) { a_[i][0] = 0ULL; a_[i][1] = 0ULL; }
        #pragma unroll 8
        for (int k = 0; k < 64; k++) {
            float af[TM], bf[TN];
            *(float4*)&af[0] = *(const float4*)&actIn[k * DEC_RS + ty * TM];
            *(float4*)&af[4] = *(const float4*)&actIn[k * DEC_RS + ty * TM + 4];
            *(float4*)&bf[0] = *(const float4*)&W[k * 64 + tx * TN];
            u64 a2[TM], b2[2];
            #pragma unroll
            for (int i = 0; i < TM; i++) a2[i] = dup2(af[i]);
            b2[0] = pk2(bf[0], bf[1]); b2[1] = pk2(bf[2], bf[3]);
            #pragma unroll
            for (int i = 0; i < TM; i++) { fma2(a_[i][0], a2[i], b2[0]); fma2(a_[i][1], a2[i], b2[1]); }
        }
        float vb[TM][TN];
        float bbl[TN];
        #pragma unroll
        for (int j = 0; j < TN; j++) bbl[j] = __ldg(&bl[tx * TN + j]);
        #pragma unroll
        for (int i = 0; i < TM; i++) {
            unpk2(vb[i][0], vb[i][1], a_[i][0]);
            unpk2(vb[i][2], vb[i][3], a_[i][1]);
            #pragma unroll
            for (int j = 0; j < TN; j++) vb[i][j] = fmaxf(vb[i][j] + bbl[j], 0.f);
        }
        #pragma unroll
        for (int j = 0; j < TN; j++) {
            int col = tx * TN + j;
            *(float4*)&actOut[col * DEC_RS + ty * TM] =
                make_float4(vb[0][j], vb[1][j], vb[2][j], vb[3][j]);
            *(float4*)&actOut[col * DEC_RS + ty * TM + 4] =
                make_float4(vb[4][j], vb[5][j], vb[6][j], vb[7][j]);
        }
    };

    layer(sA0, sW2, bm2, sA1);   // L2
    __syncthreads();

    // ---- L3 + final(Wm4,bm4) + argmax ----
    {
        u64 a_[TM][2];
        #pragma unroll
        for (int i = 0; i < TM; i++) { a_[i][0] = 0ULL; a_[i][1] = 0ULL; }
        #pragma unroll 8
        for (int k = 0; k < 64; k++) {
            float af[TM], bf[TN];
            *(float4*)&af[0] = *(const float4*)&sA1[k * DEC_RS + ty * TM];
            *(float4*)&af[4] = *(const float4*)&sA1[k * DEC_RS + ty * TM + 4];
            *(float4*)&bf[0] = *(const float4*)&sW3[k * 64 + tx * TN];
            u64 a2[TM], b2[2];
            #pragma unroll
            for (int i = 0; i < TM; i++) a2[i] = dup2(af[i]);
            b2[0] = pk2(bf[0], bf[1]); b2[1] = pk2(bf[2], bf[3]);
            #pragma unroll
            for (int i = 0; i < TM; i++) { fma2(a_[i][0], a2[i], b2[0]); fma2(a_[i][1], a2[i], b2[1]); }
        }
        float bbl[TN];
        #pragma unroll
        for (int j = 0; j < TN; j++) bbl[j] = __ldg(&bm3[tx * TN + j]);
        float wf[TN][3];
        #pragma unroll
        for (int j = 0; j < TN; j++)
            #pragma unroll
            for (int c = 0; c < 3; c++)
                wf[j][c] = __ldg(&Wm4[(tx * TN + j) * 3 + c]);
        #pragma unroll
        for (int i = 0; i < TM; i++) {
            int gr = rowBase + ty * TM + i;
            float v0, v1, v2, v3;
            unpk2(v0, v1, a_[i][0]);
            unpk2(v2, v3, a_[i][1]);
            v0 = fmaxf(v0 + bbl[0], 0.f); v1 = fmaxf(v1 + bbl[1], 0.f);
            v2 = fmaxf(v2 + bbl[2], 0.f); v3 = fmaxf(v3 + bbl[3], 0.f);
            float o0 = v0 * wf[0][0] + v1 * wf[1][0] + v2 * wf[2][0] + v3 * wf[3][0];
            float o1 = v0 * wf[0][1] + v1 * wf[1][1] + v2 * wf[2][1] + v3 * wf[3][1];
            float o2 = v0 * wf[0][2] + v1 * wf[1][2] + v2 * wf[2][2] + v3 * wf[3][2];
            #pragma unroll
            for (int off = 8; off; off >>= 1) {
                o0 += __shfl_xor_sync(0xffffffffu, o0, off);
                o1 += __shfl_xor_sync(0xffffffffu, o1, off);
                o2 += __shfl_xor_sync(0xffffffffu, o2, off);
            }
            if (tx == 0 && gr < M) {
                o0 += __ldg(&bm4[0]); o1 += __ldg(&bm4[1]); o2 += __ldg(&bm4[2]);
                int   idx  = 0;
                float best = o0;
                if (o1 > best) { best = o1; idx = 1; }
                if (o2 > best) { best = o2; idx = 2; }
                outF[gr]           = (float)idx;
                outF[L_EDGES + gr] = best;
                outF[2 * L_EDGES + gr * 3 + 0] = o0;
                outF[2 * L_EDGES + gr * 3 + 1] = o1;
                outF[2 * L_EDGES + gr * 3 + 2] = o2;
            }
        }
    }
}

// ---------------- CSR build ----------------
__global__ void k_cnt_all(const int* __restrict__ hn, const int* __restrict__ he,
                          const int* __restrict__ ei) {
    int i = blockIdx.x * blockDim.x + threadIdx.x;
    if (i < N_PAIRS) {
        atomicAdd(&c_cnt_nd[hn[i]], 1);
        atomicAdd(&c_cnt_he[he[i]], 1);
    }
    int t = i - N_PAIRS;
    if (t >= 0 && t < E2) {
        int d = (t < E_EDGES) ? ei[E_EDGES + t] : (t - E_EDGES);
        atomicAdd(&c_cnt_g[d], 1);
    }
}

__device__ void scan_block(const int* __restrict__ in, int* __restrict__ off,
                           int* __restrict__ cur, int n) {
    const int tid = threadIdx.x;
    const int lane = tid & 31, wid = tid >> 5;
    __shared__ int wsums[32];
    __shared__ int s_tot;
    int carry = 0;
    for (int base = 0; base < n; base += 8192) {
        int i0 = base + tid * 8;
        int o[8], v[8];
        #pragma unroll
        for (int j = 0; j < 8; j++) o[j] = (i0 + j < n) ? in[i0 + j] : 0;
        v[0] = o[0];
        #pragma unroll
        for (int j = 1; j < 8; j++) v[j] = v[j - 1] + o[j];
        int tsum = v[7];
        int x = tsum;
        #pragma unroll
        for (int d = 1; d < 32; d <<= 1) {
            int y = __shfl_up_sync(0xffffffffu, x, d);
            if (lane >= d) x += y;
        }
        if (lane == 31) wsums[wid] = x;
        __syncthreads();
        if (wid == 0) {
            int y = wsums[lane], z = y;
            #pragma unroll
            for (int d = 1; d < 32; d <<= 1) {
                int u = __shfl_up_sync(0xffffffffu, z, d);
                if (lane >= d) z += u;
            }
            if (lane == 31) s_tot = z;
            wsums[lane] = z - y;
        }
        __syncthreads();
        int offv = carry + wsums[wid] + (x - tsum);
        #pragma unroll
        for (int j = 0; j < 8; j++) {
            if (i0 + j < n) {
                int e = offv + v[j] - o[j];
                off[i0 + j] = e;
                cur[i0 + j] = e;
            }
        }
        carry += s_tot;
        __syncthreads();
    }
}
__global__ void __launch_bounds__(1024) k_scan3() {
    if (blockIdx.x == 0)      scan_block(c_cnt_he, c_off_he, c_cur_he, N_HE);
    else if (blockIdx.x == 1) scan_block(c_cnt_nd, c_off_nd, c_cur_nd, N_NODES);
    else                      scan_block(c_cnt_g,  c_off_g,  c_cur_g,  N_NODES);
}

__global__ void k_fill_all(const int* __restrict__ hn, const int* __restrict__ he,
                           const int* __restrict__ ei) {
    int i = blockIdx.x * blockDim.x + threadIdx.x;
    if (i < N_PAIRS) {
        int n = hn[i], e = he[i];
        c_val_he[atomicAdd(&c_cur_he[e], 1)] = n;
        c_val_nd[atomicAdd(&c_cur_nd[n], 1)] = e;
    }
    int t = i - N_PAIRS;
    if (t >= 0 && t < E2) {
        int s, d;
        if (t < E_EDGES) { s = ei[t]; d = ei[E_EDGES + t]; } else { s = d = t - E_EDGES; }
        c_val_g[atomicAdd(&c_cur_g[d], 1)] = s;
    }
}

// ---------------- hypergraph conv ----------------
__global__ void k_hc_edge_gather128(const float* __restrict__ x) {
    int gw = (blockIdx.x * blockDim.x + threadIdx.x) >> 5;
    int lane = threadIdx.x & 31;
    if (gw >= N_HE) return;
    int deg = c_cnt_he[gw], start = c_off_he[gw];
    float4 a = {0, 0, 0, 0};
    int i = 0;
    for (; i + 4 <= deg; i += 4) {
        int n0 = c_val_he[start + i],     n1 = c_val_he[start + i + 1];
        int n2 = c_val_he[start + i + 2], n3 = c_val_he[start + i + 3];
        float4 x0 = ((const float4*)(x + (size_t)n0 * 128))[lane];
        float4 x1 = ((const float4*)(x + (size_t)n1 * 128))[lane];
        float4 x2 = ((const float4*)(x + (size_t)n2 * 128))[lane];
        float4 x3 = ((const float4*)(x + (size_t)n3 * 128))[lane];
        f4add(a, x0); f4add(a, x1); f4add(a, x2); f4add(a, x3);
    }
    for (; i < deg; i++) {
        f4add(a, ((const float4*)(x + (size_t)c_val_he[start + i] * 128))[lane]);
    }
    float binv = deg > 0 ? 1.f / (float)deg : 0.f;
    a.x *= binv; a.y *= binv; a.z *= binv; a.w *= binv;
    ((float4*)(g_h0 + (size_t)gw * 128))[lane] = a;
}
// 2 warps per node: each warp covers 128 of the 256 channels
__global__ void k_hc_node_gather(const float* __restrict__ b1) {
    int gw = (blockIdx.x * blockDim.x + threadIdx.x) >> 5;
    int lane = threadIdx.x & 31;
    int node = gw >> 1;
    int half = gw & 1;
    if (node >= N_NODES) return;
    int deg = c_cnt_nd[node], start = c_off_nd[node];
    const int co = lane + 32 * half;
    float4 a = {0, 0, 0, 0};
    int i = 0;
    for (; i + 4 <= deg; i += 4) {
        const float4* p0 = (const float4*)(g_m + (size_t)c_val_nd[start + i] * 256);
        const float4* p1 = (const float4*)(g_m + (size_t)c_val_nd[start + i + 1] * 256);
        const float4* p2 = (const float4*)(g_m + (size_t)c_val_nd[start + i + 2] * 256);
        const float4* p3 = (const float4*)(g_m + (size_t)c_val_nd[start + i + 3] * 256);
        float4 x0 = p0[co], x1 = p1[co], x2 = p2[co], x3 = p3[co];
        f4add(a, x0); f4add(a, x1); f4add(a, x2); f4add(a, x3);
    }
    for (; i < deg; i++) {
        f4add(a, ((const float4*)(g_m + (size_t)c_val_nd[start + i] * 256))[co]);
    }
    float dinv = deg > 0 ? 1.f / (float)deg : 0.f;
    float4 bb = __ldg((const float4*)b1 + co);
    float4 r;
    r.x = fmaxf(a.x * dinv + bb.x, 0.f); r.y = fmaxf(a.y * dinv + bb.y, 0.f);
    r.z = fmaxf(a.z * dinv + bb.z, 0.f); r.w = fmaxf(a.w * dinv + bb.w, 0.f);
    ((float4*)(g_h1 + (size_t)node * 256))[co] = r;
}

// ---------------- GAT ----------------
__global__ void k_dots256(const float* __restrict__ a_s, const float* __restrict__ a_d) {
    int gw = (blockIdx.x * blockDim.x + threadIdx.x) >> 5;
    int lane = threadIdx.x & 31;
    if (gw >= N_NODES) return;
    float s0 = 0.f, s1 = 0.f;
    const float4* h = (const float4*)(g_hg + (size_t)gw * 256);
    #pragma unroll
    for (int j = lane; j < 64; j += 32) {
        float4 v = h[j];
        float4 as4 = __ldg((const float4*)a_s + j);
        float4 ad4 = __ldg((const float4*)a_d + j);
        s0 += v.x * as4.x + v.y * as4.y + v.z * as4.z + v.w * as4.w;
        s1 += v.x * ad4.x + v.y * ad4.y + v.z * ad4.z + v.w * ad4.w;
    }
    #pragma unroll
    for (int off = 16; off; off >>= 1) {
        s0 += __shfl_down_sync(0xffffffffu, s0, off);
        s1 += __shfl_down_sync(0xffffffffu, s1, off);
    }
    if (lane == 0) { g_as[gw] = s0; g_ad[gw] = s1; }
}

// GAT1 aggr: 2 warps per node; each warp gathers its 128-channel half
__global__ void k_gat_aggr256(const float* __restrict__ bias, float* __restrict__ dst) {
    int gw = (blockIdx.x * blockDim.x + threadIdx.x) >> 5;
    int lane = threadIdx.x & 31;
    int node = gw >> 1;
    int half = gw & 1;
    if (node >= N_NODES) return;
    int deg = c_cnt_g[node], start = c_off_g[node];
    float adst = g_ad[node];
    float mx = -1e30f;
    for (int i = lane; i < deg; i += 32)
        mx = fmaxf(mx, lrelu02(g_as[c_val_g[start + i]] + adst));
    #pragma unroll
    for (int off = 16; off; off >>= 1)
        mx = fmaxf(mx, __shfl_xor_sync(0xffffffffu, mx, off));
    float sm = 0.f;
    for (int i = lane; i < deg; i += 32)
        sm += expf(lrelu02(g_as[c_val_g[start + i]] + adst) - mx);
    #pragma unroll
    for (int off = 16; off; off >>= 1)
        sm += __shfl_xor_sync(0xffffffffu, sm, off);
    float inv = 1.f / (sm + 1e-16f);
    const int co = lane + 32 * half;
    float4 a = {0, 0, 0, 0};
    int i = 0;
    for (; i + 4 <= deg; i += 4) {
        int s0 = c_val_g[start + i],     s1 = c_val_g[start + i + 1];
        int s2 = c_val_g[start + i + 2], s3 = c_val_g[start + i + 3];
        float w0 = expf(lrelu02(g_as[s0] + adst) - mx) * inv;
        float w1 = expf(lrelu02(g_as[s1] + adst) - mx) * inv;
        float w2 = expf(lrelu02(g_as[s2] + adst) - mx) * inv;
        float w3 = expf(lrelu02(g_as[s3] + adst) - mx) * inv;
        float4 x0 = ((const float4*)(g_hg + (size_t)s0 * 256))[co];
        float4 x1 = ((const float4*)(g_hg + (size_t)s1 * 256))[co];
        float4 x2 = ((const float4*)(g_hg + (size_t)s2 * 256))[co];
        float4 x3 = ((const float4*)(g_hg + (size_t)s3 * 256))[co];
        f4fma(a, w0, x0); f4fma(a, w1, x1); f4fma(a, w2, x2); f4fma(a, w3, x3);
    }
    for (; i < deg; i++) {
        int s0 = c_val_g[start + i];
        float w0 = expf(lrelu02(g_as[s0] + adst) - mx) * inv;
        f4fma(a, w0, ((const float4*)(g_hg + (size_t)s0 * 256))[co]);
    }
    float4 bb = __ldg((const float4*)bias + co);
    float4 r;
    r.x = fmaxf(a.x + bb.x, 0.f); r.y = fmaxf(a.y + bb.y, 0.f);
    r.z = fmaxf(a.z + bb.z, 0.f); r.w = fmaxf(a.w + bb.w, 0.f);
    ((float4*)(dst + (size_t)node * 256))[co] = r;
}

// GAT2 aggr: warp per node, 64 channels
__global__ void k_gat_aggr64(const float* __restrict__ bias, float* __restrict__ dst) {
    int gw = (blockIdx.x * blockDim.x + threadIdx.x) >> 5;
    int lane = threadIdx.x & 31;
    if (gw >= N_NODES) return;
    int deg = c_cnt_g[gw], start = c_off_g[gw];
    float adst = g_ad[gw];
    float mx = -1e30f;
    for (int i = lane; i < deg; i += 32)
        mx = fmaxf(mx, lrelu02(g_as[c_val_g[start + i]] + adst));
    #pragma unroll
    for (int off = 16; off; off >>= 1)
        mx = fmaxf(mx, __shfl_xor_sync(0xffffffffu, mx, off));
    float sm = 0.f;
    for (int i = lane; i < deg; i += 32)
        sm += expf(lrelu02(g_as[c_val_g[start + i]] + adst) - mx);
    #pragma unroll
    for (int off = 16; off; off >>= 1)
        sm += __shfl_xor_sync(0xffffffffu, sm, off);
    float inv = 1.f / (sm + 1e-16f);
    float2 acc = {0, 0};
    int i = 0;
    for (; i + 4 <= deg; i += 4) {
        int s0 = c_val_g[start + i],     s1 = c_val_g[start + i + 1];
        int s2 = c_val_g[start + i + 2], s3 = c_val_g[start + i + 3];
        float w0 = expf(lrelu02(g_as[s0] + adst) - mx) * inv;
        float w1 = expf(lrelu02(g_as[s1] + adst) - mx) * inv;
        float w2 = expf(lrelu02(g_as[s2] + adst) - mx) * inv;
        float w3 = expf(lrelu02(g_as[s3] + adst) - mx) * inv;
        float2 x0 = *(const float2*)(g_hg + (size_t)s0 * 64 + 2 * lane);
        float2 x1 = *(const float2*)(g_hg + (size_t)s1 * 64 + 2 * lane);
        float2 x2 = *(const float2*)(g_hg + (size_t)s2 * 64 + 2 * lane);
        float2 x3 = *(const float2*)(g_hg + (size_t)s3 * 64 + 2 * lane);
        acc.x = fmaf(w0, x0.x, acc.x); acc.y = fmaf(w0, x0.y, acc.y);
        acc.x = fmaf(w1, x1.x, acc.x); acc.y = fmaf(w1, x1.y, acc.y);
        acc.x = fmaf(w2, x2.x, acc.x); acc.y = fmaf(w2, x2.y, acc.y);
        acc.x = fmaf(w3, x3.x, acc.x); acc.y = fmaf(w3, x3.y, acc.y);
    }
    for (; i < deg; i++) {
        int s0 = c_val_g[start + i];
        float w0 = expf(lrelu02(g_as[s0] + adst) - mx) * inv;
        float2 x0 = *(const float2*)(g_hg + (size_t)s0 * 64 + 2 * lane);
        acc.x = fmaf(w0, x0.x, acc.x); acc.y = fmaf(w0, x0.y, acc.y);
    }
    float2 bb = *(const float2*)(bias + 2 * lane);
    float2 r;
    r.x = fmaxf(acc.x + bb.x, 0.f);
    r.y = fmaxf(acc.y + bb.y, 0.f);
    *(float2*)(dst + (size_t)gw * 64 + 2 * lane) = r;
}

// ---------------- host launch ----------------
static inline int cdiv(int a, int b) { return (a + b - 1) / b; }

extern "C" void kernel_launch(void* const* d_in, const int* in_sizes, int n_in,
                              void* d_out, int out_size) {
    const float* x   = (const float*)d_in[0];
    const int*   ei  = (const int*)d_in[1];
    const int*   hn  = (const int*)d_in[2];
    const int*   he  = (const int*)d_in[3];
    const int*   eli = (const int*)d_in[4];
    const float* W1  = (const float*)d_in[5];
    const float* b1  = (const float*)d_in[6];
    const float* W2  = (const float*)d_in[7];
    const float* a2s = (const float*)d_in[8];
    const float* a2d = (const float*)d_in[9];
    const float* b2  = (const float*)d_in[10];
    const float* W3  = (const float*)d_in[11];
    const float* a3s = (const float*)d_in[12];
    const float* a3d = (const float*)d_in[13];
    const float* b3  = (const float*)d_in[14];
    const float* Wm1 = (const float*)d_in[15];
    const float* bm1 = (const float*)d_in[16];
    const float* Wm2 = (const float*)d_in[17];
    const float* bm2 = (const float*)d_in[18];
    const float* Wm3 = (const float*)d_in[19];
    const float* bm3 = (const float*)d_in[20];
    const float* Wm4 = (const float*)d_in[21];
    const float* bm4 = (const float*)d_in[22];
    float* out = (float*)d_out;

    void *p_cnt, *p_h0, *p_h1, *p_hg, *p_z, *p_m, *p_as, *p_ad;
    cudaGetSymbolAddress(&p_cnt, c_cnt);
    cudaGetSymbolAddress(&p_h0, g_h0);
    cudaGetSymbolAddress(&p_h1, g_h1);
    cudaGetSymbolAddress(&p_hg, g_hg);
    cudaGetSymbolAddress(&p_z,  g_z);
    cudaGetSymbolAddress(&p_m,  g_m);
    cudaGetSymbolAddress(&p_as, g_as);
    cudaGetSymbolAddress(&p_ad, g_ad);

    const int TB = 256;

    cudaFuncSetAttribute(k_decode, cudaFuncAttributeMaxDynamicSharedMemorySize, DEC_SMEM);

    // ===== CSR builds (single memset) =====
    cudaMemsetAsync(p_cnt, 0, sizeof(int) * (N_HE + 2 * N_NODES), 0);
    k_cnt_all<<<cdiv(N_PAIRS + E2, TB), TB>>>(hn, he, ei);
    k_scan3<<<3, 1024>>>();
    k_fill_all<<<cdiv(N_PAIRS + E2, TB), TB>>>(hn, he, ei);

    // ===== hypergraph conv: gather x (128d) -> GEMM on hyperedges -> node gather =====
    k_hc_edge_gather128<<<cdiv(N_HE * 32, TB), TB>>>(x);
    sgemm<128, 128, 16, 8, 8, false, false><<<dim3(2, cdiv(N_HE, 128)), 256>>>(
        (float*)p_h0, W1, (float*)p_m, N_HE, 256, 128, nullptr, nullptr, nullptr, nullptr, nullptr);
    k_hc_node_gather<<<cdiv(N_NODES * 2 * 32, TB), TB>>>(b1);

    // ===== GAT layer 1 (256 -> 256) =====
    sgemm<128, 128, 16, 8, 8, false, false><<<dim3(2, cdiv(N_NODES, 128)), 256>>>(
        (float*)p_h1, W2, (float*)p_hg, N_NODES, 256, 256, nullptr, nullptr, nullptr, nullptr, nullptr);
    k_dots256<<<cdiv(N_NODES * 32, TB), TB>>>(a2s, a2d);
    k_gat_aggr256<<<cdiv(N_NODES * 2 * 32, TB), TB>>>(b2, (float*)p_h1);

    // ===== GAT layer 2 (256 -> 64), dots fused into GEMM epilogue (no atomics) =====
    sgemm<128, 64, 16, 8, 4, false, true><<<dim3(1, cdiv(N_NODES, 128)), 256>>>(
        (float*)p_h1, W3, (float*)p_hg, N_NODES, 64, 256, nullptr,
        a3s, a3d, (float*)p_as, (float*)p_ad);
    k_gat_aggr64<<<cdiv(N_NODES * 32, TB), TB>>>(b3, (float*)p_z);

    // ===== decode: single fused kernel =====
    k_decode<<<cdiv(L_EDGES, 128), 256, DEC_SMEM>>>(
        (float*)p_z, Wm1, bm1, Wm2, bm2, Wm3, bm3, Wm4, bm4, eli, out);
}

// round 16
// speedup vs baseline: 1.0204x; 1.0204x over previous
#include <cuda_runtime.h>
#include <math.h>

#define N_NODES   50000
#define N_HE      20000
#define N_PAIRS   400000
#define E_EDGES   800000
#define E2        (E_EDGES + N_NODES)
#define L_EDGES   100000

// ---------------- scratch (device globals; no runtime allocation) ----------------
__device__ float g_h0[N_NODES * 256];   // hconv: m128 staging
__device__ float g_m [N_HE    * 256];   // hyperedge messages post-GEMM
__device__ float g_h1[N_NODES * 256];   // activations; decode: MLP ping-pong buffers
__device__ float g_hg[N_NODES * 256];   // GEMM output features
__device__ float g_as[N_NODES];
__device__ float g_ad[N_NODES];
__device__ float g_z [N_NODES * 64];

// CSR: single backing array for counts (one memset)
__device__ int c_cnt[N_HE + N_NODES + N_NODES];
#define c_cnt_he (c_cnt)
#define c_cnt_nd (c_cnt + N_HE)
#define c_cnt_g  (c_cnt + N_HE + N_NODES)
__device__ int c_off_he[N_HE],    c_cur_he[N_HE],    c_val_he[N_PAIRS];
__device__ int c_off_nd[N_NODES], c_cur_nd[N_NODES], c_val_nd[N_PAIRS];
__device__ int c_off_g [N_NODES], c_cur_g [N_NODES], c_val_g [E2];

typedef unsigned long long u64;

__device__ __forceinline__ float lrelu02(float x) { return x > 0.f ? x : 0.2f * x; }
__device__ __forceinline__ void f4add(float4& a, const float4 b) {
    a.x += b.x; a.y += b.y; a.z += b.z; a.w += b.w;
}
__device__ __forceinline__ void f4fma(float4& a, float w, const float4 b) {
    a.x = fmaf(w, b.x, a.x); a.y = fmaf(w, b.y, a.y);
    a.z = fmaf(w, b.z, a.z); a.w = fmaf(w, b.w, a.w);
}
// ---- packed fp32x2 (Blackwell FFMA2) ----
__device__ __forceinline__ u64 pk2(float lo, float hi) {
    u64 r; asm("mov.b64 %0, {%1, %2};" : "=l"(r) : "f"(lo), "f"(hi)); return r;
}
__device__ __forceinline__ u64 dup2(float x) { return pk2(x, x); }
__device__ __forceinline__ void unpk2(float& lo, float& hi, u64 v) {
    asm("mov.b64 {%0, %1}, %2;" : "=f"(lo), "=f"(hi) : "l"(v));
}
__device__ __forceinline__ void fma2(u64& d, u64 a, u64 b) {
    asm("fma.rn.f32x2 %0, %1, %2, %0;" : "+l"(d) : "l"(a), "l"(b));
}

// ---------------- GEMM: C[M,N] = A[M,K] @ B[K,N], fp32, f32x2 core, double-buffered.
// EPI: fused C = relu(C + bias[col]).
// GATHER: A row gr is concat(src[gidx[gr]], dst[gidx[M+gr]]) from A (64-dim rows).
// FIN: (BN==N==64, grid.x==1) final Wf[64x3]+bf, argmax -> outF; skips C store.
// DOTS: (BN==N, grid.x==1) row dots with av_s/av_d -> dot_s/dot_d (C store kept).
template<int BM, int BN, int BK, int TM, int TN, bool EPI, bool GATHER, bool FIN, bool DOTS>
__global__ void __launch_bounds__((BM / TM) * (BN / TN))
sgemm(const float* __restrict__ A, const float* __restrict__ B, float* __restrict__ C,
      int M, int N, int K, const float* __restrict__ bias, const int* __restrict__ gidx,
      const float* __restrict__ Wf, const float* __restrict__ bf, float* __restrict__ outF,
      const float* __restrict__ av_s, const float* __restrict__ av_d,
      float* __restrict__ dot_s, float* __restrict__ dot_d) {
    constexpr int NT = (BM / TM) * (BN / TN);
    constexpr int LA = BM * BK / 4 / NT;
    constexpr int LB = BK * BN / 4 / NT;
    __shared__ float As[2][BK][BM + 4];
    __shared__ float Bs[2][BK][BN];
    const int tid = threadIdx.x;
    const int tx = tid % (BN / TN);
    const int ty = tid / (BN / TN);
    const int rowBase = blockIdx.y * BM, colBase = blockIdx.x * BN;
    float4 ra[LA], rb[LB];

    auto loadA = [&](int k0) {
        #pragma unroll
        for (int s = 0; s < LA; s++) {
            int f = tid + s * NT;
            int r = f / (BK / 4), c = (f % (BK / 4)) * 4;
            int gr = rowBase + r;
            if constexpr (GATHER) {
                if (gr < M) {
                    int col = k0 + c;
                    int node = (col < 64) ? __ldg(&gidx[gr]) : __ldg(&gidx[M + gr]);
                    ra[s] = *(const float4*)&A[(size_t)node * 64 + (col & 63)];
                } else {
                    ra[s] = make_float4(0.f, 0.f, 0.f, 0.f);
                }
            } else {
                ra[s] = (gr < M) ? *(const float4*)&A[(size_t)gr * K + k0 + c]
                                 : make_float4(0.f, 0.f, 0.f, 0.f);
            }
        }
    };
    auto loadB = [&](int k0) {
        #pragma unroll
        for (int s = 0; s < LB; s++) {
            int f = tid + s * NT;
            int r = f / (BN / 4), c = (f % (BN / 4)) * 4;
            rb[s] = *(const float4*)&B[(size_t)(k0 + r) * N + colBase + c];
        }
    };
    auto stA = [&](int buf) {
        #pragma unroll
        for (int s = 0; s < LA; s++) {
            int f = tid + s * NT;
            int r = f / (BK / 4), c = (f % (BK / 4)) * 4;
            As[buf][c + 0][r] = ra[s].x; As[buf][c + 1][r] = ra[s].y;
            As[buf][c + 2][r] = ra[s].z; As[buf][c + 3][r] = ra[s].w;
        }
    };
    auto stB = [&](int buf) {
        #pragma unroll
        for (int s = 0; s < LB; s++) {
            int f = tid + s * NT;
            int r = f / (BN / 4), c = (f % (BN / 4)) * 4;
            *(float4*)&Bs[buf][r][c] = rb[s];
        }
    };

    u64 acc[TM][TN / 2];
    #pragma unroll
    for (int i = 0; i < TM; i++)
        #pragma unroll
        for (int j = 0; j < TN / 2; j++) acc[i][j] = 0ULL;

    loadA(0); loadB(0); stA(0); stB(0);
    __syncthreads();
    const int T = K / BK;
    int cur = 0;
    for (int t = 0; t < T; t++) {
        if (t + 1 < T) { loadA((t + 1) * BK); loadB((t + 1) * BK); }
        #pragma unroll
        for (int k = 0; k < BK; k++) {
            float af[TM], bf_[TN];
            #pragma unroll
            for (int i = 0; i < TM; i += 4)
                *(float4*)&af[i] = *(const float4*)&As[cur][k][ty * TM + i];
            #pragma unroll
            for (int j = 0; j < TN; j += 4)
                *(float4*)&bf_[j] = *(const float4*)&Bs[cur][k][tx * TN + j];
            u64 a2[TM], b2[TN / 2];
            #pragma unroll
            for (int i = 0; i < TM; i++) a2[i] = dup2(af[i]);
            #pragma unroll
            for (int j = 0; j < TN / 2; j++) b2[j] = pk2(bf_[2 * j], bf_[2 * j + 1]);
            #pragma unroll
            for (int i = 0; i < TM; i++)
                #pragma unroll
                for (int j = 0; j < TN / 2; j++) fma2(acc[i][j], a2[i], b2[j]);
        }
        if (t + 1 < T) {
            stA(cur ^ 1); stB(cur ^ 1);
            __syncthreads();
            cur ^= 1;
        }
    }
    float bb[TN];
    if constexpr (EPI) {
        #pragma unroll
        for (int j = 0; j < TN; j++) bb[j] = __ldg(&bias[colBase + tx * TN + j]);
    }
    float wf[TN][3];
    if constexpr (FIN) {
        #pragma unroll
        for (int j = 0; j < TN; j++)
            #pragma unroll
            for (int c = 0; c < 3; c++)
                wf[j][c] = __ldg(&Wf[(tx * TN + j) * 3 + c]);
    }
    float avs[TN], avd[TN];
    if constexpr (DOTS) {
        #pragma unroll
        for (int j = 0; j < TN; j++) {
            avs[j] = __ldg(&av_s[tx * TN + j]);
            avd[j] = __ldg(&av_d[tx * TN + j]);
        }
    }
    #pragma unroll
    for (int i = 0; i < TM; i++) {
        int gr = rowBase + ty * TM + i;
        float vbuf[TN];
        #pragma unroll
        for (int j = 0; j < TN / 2; j++) unpk2(vbuf[2 * j], vbuf[2 * j + 1], acc[i][j]);
        if constexpr (EPI) {
            #pragma unroll
            for (int j = 0; j < TN; j++) vbuf[j] = fmaxf(vbuf[j] + bb[j], 0.f);
        }
        if constexpr (FIN) {
            float o0 = 0.f, o1 = 0.f, o2 = 0.f;
            #pragma unroll
            for (int j = 0; j < TN; j++) {
                o0 = fmaf(vbuf[j], wf[j][0], o0);
                o1 = fmaf(vbuf[j], wf[j][1], o1);
                o2 = fmaf(vbuf[j], wf[j][2], o2);
            }
            #pragma unroll
            for (int off = 8; off; off >>= 1) {
                o0 += __shfl_xor_sync(0xffffffffu, o0, off);
                o1 += __shfl_xor_sync(0xffffffffu, o1, off);
                o2 += __shfl_xor_sync(0xffffffffu, o2, off);
            }
            if (tx == 0 && gr < M) {
                o0 += __ldg(&bf[0]); o1 += __ldg(&bf[1]); o2 += __ldg(&bf[2]);
                int   idx  = 0;
                float best = o0;
                if (o1 > best) { best = o1; idx = 1; }
                if (o2 > best) { best = o2; idx = 2; }
                outF[gr]                = (float)idx;
                outF[L_EDGES + gr]      = best;
                outF[2 * L_EDGES + gr * 3 + 0] = o0;
                outF[2 * L_EDGES + gr * 3 + 1] = o1;
                outF[2 * L_EDGES + gr * 3 + 2] = o2;
            }
        } else {
            if (gr < M) {
                #pragma unroll
                for (int j = 0; j < TN / 4; j++)
                    *(float4*)&C[(size_t)gr * N + colBase + tx * TN + 4 * j] =
                        make_float4(vbuf[4 * j], vbuf[4 * j + 1], vbuf[4 * j + 2], vbuf[4 * j + 3]);
            }
            if constexpr (DOTS) {
                float ps = 0.f, pd = 0.f;
                #pragma unroll
                for (int j = 0; j < TN; j++) {
                    ps = fmaf(vbuf[j], avs[j], ps);
                    pd = fmaf(vbuf[j], avd[j], pd);
                }
                #pragma unroll
                for (int off = 8; off; off >>= 1) {
                    ps += __shfl_xor_sync(0xffffffffu, ps, off);
                    pd += __shfl_xor_sync(0xffffffffu, pd, off);
                }
                if (tx == 0 && gr < M) { dot_s[gr] = ps; dot_d[gr] = pd; }
            }
        }
    }
}

// ---------------- CSR build ----------------
__global__ void k_cnt_all(const int* __restrict__ hn, const int* __restrict__ he,
                          const int* __restrict__ ei) {
    int i = blockIdx.x * blockDim.x + threadIdx.x;
    if (i < N_PAIRS) {
        atomicAdd(&c_cnt_nd[hn[i]], 1);
        atomicAdd(&c_cnt_he[he[i]], 1);
    }
    int t = i - N_PAIRS;
    if (t >= 0 && t < E2) {
        int d = (t < E_EDGES) ? ei[E_EDGES + t] : (t - E_EDGES);
        atomicAdd(&c_cnt_g[d], 1);
    }
}

__device__ void scan_block(const int* __restrict__ in, int* __restrict__ off,
                           int* __restrict__ cur, int n) {
    const int tid = threadIdx.x;
    const int lane = tid & 31, wid = tid >> 5;
    __shared__ int wsums[32];
    __shared__ int s_tot;
    int carry = 0;
    for (int base = 0; base < n; base += 8192) {
        int i0 = base + tid * 8;
        int o[8], v[8];
        #pragma unroll
        for (int j = 0; j < 8; j++) o[j] = (i0 + j < n) ? in[i0 + j] : 0;
        v[0] = o[0];
        #pragma unroll
        for (int j = 1; j < 8; j++) v[j] = v[j - 1] + o[j];
        int tsum = v[7];
        int x = tsum;
        #pragma unroll
        for (int d = 1; d < 32; d <<= 1) {
            int y = __shfl_up_sync(0xffffffffu, x, d);
            if (lane >= d) x += y;
        }
        if (lane == 31) wsums[wid] = x;
        __syncthreads();
        if (wid == 0) {
            int y = wsums[lane], z = y;
            #pragma unroll
            for (int d = 1; d < 32; d <<= 1) {
                int u = __shfl_up_sync(0xffffffffu, z, d);
                if (lane >= d) z += u;
            }
            if (lane == 31) s_tot = z;
            wsums[lane] = z - y;
        }
        __syncthreads();
        int offv = carry + wsums[wid] + (x - tsum);
        #pragma unroll
        for (int j = 0; j < 8; j++) {
            if (i0 + j < n) {
                int e = offv + v[j] - o[j];
                off[i0 + j] = e;
                cur[i0 + j] = e;
            }
        }
        carry += s_tot;
        __syncthreads();
    }
}
__global__ void __launch_bounds__(1024) k_scan3() {
    if (blockIdx.x == 0)      scan_block(c_cnt_he, c_off_he, c_cur_he, N_HE);
    else if (blockIdx.x == 1) scan_block(c_cnt_nd, c_off_nd, c_cur_nd, N_NODES);
    else                      scan_block(c_cnt_g,  c_off_g,  c_cur_g,  N_NODES);
}

__global__ void k_fill_all(const int* __restrict__ hn, const int* __restrict__ he,
                           const int* __restrict__ ei) {
    int i = blockIdx.x * blockDim.x + threadIdx.x;
    if (i < N_PAIRS) {
        int n = hn[i], e = he[i];
        c_val_he[atomicAdd(&c_cur_he[e], 1)] = n;
        c_val_nd[atomicAdd(&c_cur_nd[n], 1)] = e;
    }
    int t = i - N_PAIRS;
    if (t >= 0 && t < E2) {
        int s, d;
        if (t < E_EDGES) { s = ei[t]; d = ei[E_EDGES + t]; } else { s = d = t - E_EDGES; }
        c_val_g[atomicAdd(&c_cur_g[d], 1)] = s;
    }
}

// ---------------- hypergraph conv ----------------
__global__ void k_hc_edge_gather128(const float* __restrict__ x) {
    int gw = (blockIdx.x * blockDim.x + threadIdx.x) >> 5;
    int lane = threadIdx.x & 31;
    if (gw >= N_HE) return;
    int deg = c_cnt_he[gw], start = c_off_he[gw];
    float4 a = {0, 0, 0, 0};
    int i = 0;
    for (; i + 4 <= deg; i += 4) {
        int n0 = c_val_he[start + i],     n1 = c_val_he[start + i + 1];
        int n2 = c_val_he[start + i + 2], n3 = c_val_he[start + i + 3];
        float4 x0 = ((const float4*)(x + (size_t)n0 * 128))[lane];
        float4 x1 = ((const float4*)(x + (size_t)n1 * 128))[lane];
        float4 x2 = ((const float4*)(x + (size_t)n2 * 128))[lane];
        float4 x3 = ((const float4*)(x + (size_t)n3 * 128))[lane];
        f4add(a, x0); f4add(a, x1); f4add(a, x2); f4add(a, x3);
    }
    for (; i < deg; i++) {
        f4add(a, ((const float4*)(x + (size_t)c_val_he[start + i] * 128))[lane]);
    }
    float binv = deg > 0 ? 1.f / (float)deg : 0.f;
    a.x *= binv; a.y *= binv; a.z *= binv; a.w *= binv;
    ((float4*)(g_h0 + (size_t)gw * 128))[lane] = a;
}
// 2 warps per node: each warp covers 128 of the 256 channels
__global__ void k_hc_node_gather(const float* __restrict__ b1) {
    int gw = (blockIdx.x * blockDim.x + threadIdx.x) >> 5;
    int lane = threadIdx.x & 31;
    int node = gw >> 1;
    int half = gw & 1;
    if (node >= N_NODES) return;
    int deg = c_cnt_nd[node], start = c_off_nd[node];
    const int co = lane + 32 * half;
    float4 a = {0, 0, 0, 0};
    int i = 0;
    for (; i + 4 <= deg; i += 4) {
        const float4* p0 = (const float4*)(g_m + (size_t)c_val_nd[start + i] * 256);
        const float4* p1 = (const float4*)(g_m + (size_t)c_val_nd[start + i + 1] * 256);
        const float4* p2 = (const float4*)(g_m + (size_t)c_val_nd[start + i + 2] * 256);
        const float4* p3 = (const float4*)(g_m + (size_t)c_val_nd[start + i + 3] * 256);
        float4 x0 = p0[co], x1 = p1[co], x2 = p2[co], x3 = p3[co];
        f4add(a, x0); f4add(a, x1); f4add(a, x2); f4add(a, x3);
    }
    for (; i < deg; i++) {
        f4add(a, ((const float4*)(g_m + (size_t)c_val_nd[start + i] * 256))[co]);
    }
    float dinv = deg > 0 ? 1.f / (float)deg : 0.f;
    float4 bb = __ldg((const float4*)b1 + co);
    float4 r;
    r.x = fmaxf(a.x * dinv + bb.x, 0.f); r.y = fmaxf(a.y * dinv + bb.y, 0.f);
    r.z = fmaxf(a.z * dinv + bb.z, 0.f); r.w = fmaxf(a.w * dinv + bb.w, 0.f);
    ((float4*)(g_h1 + (size_t)node * 256))[co] = r;
}

// ---------------- GAT ----------------
__global__ void k_dots256(const float* __restrict__ a_s, const float* __restrict__ a_d) {
    int gw = (blockIdx.x * blockDim.x + threadIdx.x) >> 5;
    int lane = threadIdx.x & 31;
    if (gw >= N_NODES) return;
    float s0 = 0.f, s1 = 0.f;
    const float4* h = (const float4*)(g_hg + (size_t)gw * 256);
    #pragma unroll
    for (int j = lane; j < 64; j += 32) {
        float4 v = h[j];
        float4 as4 = __ldg((const float4*)a_s + j);
        float4 ad4 = __ldg((const float4*)a_d + j);
        s0 += v.x * as4.x + v.y * as4.y + v.z * as4.z + v.w * as4.w;
        s1 += v.x * ad4.x + v.y * ad4.y + v.z * ad4.z + v.w * ad4.w;
    }
    #pragma unroll
    for (int off = 16; off; off >>= 1) {
        s0 += __shfl_down_sync(0xffffffffu, s0, off);
        s1 += __shfl_down_sync(0xffffffffu, s1, off);
    }
    if (lane == 0) { g_as[gw] = s0; g_ad[gw] = s1; }
}

// GAT1 aggr: 2 warps per node; each warp gathers its 128-channel half
__global__ void k_gat_aggr256(const float* __restrict__ bias, float* __restrict__ dst) {
    int gw = (blockIdx.x * blockDim.x + threadIdx.x) >> 5;
    int lane = threadIdx.x & 31;
    int node = gw >> 1;
    int half = gw & 1;
    if (node >= N_NODES) return;
    int deg = c_cnt_g[node], start = c_off_g[node];
    float adst = g_ad[node];
    float mx = -1e30f;
    for (int i = lane; i < deg; i += 32)
        mx = fmaxf(mx, lrelu02(g_as[c_val_g[start + i]] + adst));
    #pragma unroll
    for (int off = 16; off; off >>= 1)
        mx = fmaxf(mx, __shfl_xor_sync(0xffffffffu, mx, off));
    float sm = 0.f;
    for (int i = lane; i < deg; i += 32)
        sm += expf(lrelu02(g_as[c_val_g[start + i]] + adst) - mx);
    #pragma unroll
    for (int off = 16; off; off >>= 1)
        sm += __shfl_xor_sync(0xffffffffu, sm, off);
    float inv = 1.f / (sm + 1e-16f);
    const int co = lane + 32 * half;
    float4 a = {0, 0, 0, 0};
    int i = 0;
    for (; i + 4 <= deg; i += 4) {
        int s0 = c_val_g[start + i],     s1 = c_val_g[start + i + 1];
        int s2 = c_val_g[start + i + 2], s3 = c_val_g[start + i + 3];
        float w0 = expf(lrelu02(g_as[s0] + adst) - mx) * inv;
        float w1 = expf(lrelu02(g_as[s1] + adst) - mx) * inv;
        float w2 = expf(lrelu02(g_as[s2] + adst) - mx) * inv;
        float w3 = expf(lrelu02(g_as[s3] + adst) - mx) * inv;
        float4 x0 = ((const float4*)(g_hg + (size_t)s0 * 256))[co];
        float4 x1 = ((const float4*)(g_hg + (size_t)s1 * 256))[co];
        float4 x2 = ((const float4*)(g_hg + (size_t)s2 * 256))[co];
        float4 x3 = ((const float4*)(g_hg + (size_t)s3 * 256))[co];
        f4fma(a, w0, x0); f4fma(a, w1, x1); f4fma(a, w2, x2); f4fma(a, w3, x3);
    }
    for (; i < deg; i++) {
        int s0 = c_val_g[start + i];
        float w0 = expf(lrelu02(g_as[s0] + adst) - mx) * inv;
        f4fma(a, w0, ((const float4*)(g_hg + (size_t)s0 * 256))[co]);
    }
    float4 bb = __ldg((const float4*)bias + co);
    float4 r;
    r.x = fmaxf(a.x + bb.x, 0.f); r.y = fmaxf(a.y + bb.y, 0.f);
    r.z = fmaxf(a.z + bb.z, 0.f); r.w = fmaxf(a.w + bb.w, 0.f);
    ((float4*)(dst + (size_t)node * 256))[co] = r;
}

// GAT2 aggr: warp per node, 64 channels
__global__ void k_gat_aggr64(const float* __restrict__ bias, float* __restrict__ dst) {
    int gw = (blockIdx.x * blockDim.x + threadIdx.x) >> 5;
    int lane = threadIdx.x & 31;
    if (gw >= N_NODES) return;
    int deg = c_cnt_g[gw], start = c_off_g[gw];
    float adst = g_ad[gw];
    float mx = -1e30f;
    for (int i = lane; i < deg; i += 32)
        mx = fmaxf(mx, lrelu02(g_as[c_val_g[start + i]] + adst));
    #pragma unroll
    for (int off = 16; off; off >>= 1)
        mx = fmaxf(mx, __shfl_xor_sync(0xffffffffu, mx, off));
    float sm = 0.f;
    for (int i = lane; i < deg; i += 32)
        sm += expf(lrelu02(g_as[c_val_g[start + i]] + adst) - mx);
    #pragma unroll
    for (int off = 16; off; off >>= 1)
        sm += __shfl_xor_sync(0xffffffffu, sm, off);
    float inv = 1.f / (sm + 1e-16f);
    float2 acc = {0, 0};
    int i = 0;
    for (; i + 4 <= deg; i += 4) {
        int s0 = c_val_g[start + i],     s1 = c_val_g[start + i + 1];
        int s2 = c_val_g[start + i + 2], s3 = c_val_g[start + i + 3];
        float w0 = expf(lrelu02(g_as[s0] + adst) - mx) * inv;
        float w1 = expf(lrelu02(g_as[s1] + adst) - mx) * inv;
        float w2 = expf(lrelu02(g_as[s2] + adst) - mx) * inv;
        float w3 = expf(lrelu02(g_as[s3] + adst) - mx) * inv;
        float2 x0 = *(const float2*)(g_hg + (size_t)s0 * 64 + 2 * lane);
        float2 x1 = *(const float2*)(g_hg + (size_t)s1 * 64 + 2 * lane);
        float2 x2 = *(const float2*)(g_hg + (size_t)s2 * 64 + 2 * lane);
        float2 x3 = *(const float2*)(g_hg + (size_t)s3 * 64 + 2 * lane);
        acc.x = fmaf(w0, x0.x, acc.x); acc.y = fmaf(w0, x0.y, acc.y);
        acc.x = fmaf(w1, x1.x, acc.x); acc.y = fmaf(w1, x1.y, acc.y);
        acc.x = fmaf(w2, x2.x, acc.x); acc.y = fmaf(w2, x2.y, acc.y);
        acc.x = fmaf(w3, x3.x, acc.x); acc.y = fmaf(w3, x3.y, acc.y);
    }
    for (; i < deg; i++) {
        int s0 = c_val_g[start + i];
        float w0 = expf(lrelu02(g_as[s0] + adst) - mx) * inv;
        float2 x0 = *(const float2*)(g_hg + (size_t)s0 * 64 + 2 * lane);
        acc.x = fmaf(w0, x0.x, acc.x); acc.y = fmaf(w0, x0.y, acc.y);
    }
    float2 bb = *(const float2*)(bias + 2 * lane);
    float2 r;
    r.x = fmaxf(acc.x + bb.x, 0.f);
    r.y = fmaxf(acc.y + bb.y, 0.f);
    *(float2*)(dst + (size_t)gw * 64 + 2 * lane) = r;
}

// ---------------- host launch ----------------
static inline int cdiv(int a, int b) { return (a + b - 1) / b; }

extern "C" void kernel_launch(void* const* d_in, const int* in_sizes, int n_in,
                              void* d_out, int out_size) {
    const float* x   = (const float*)d_in[0];
    const int*   ei  = (const int*)d_in[1];
    const int*   hn  = (const int*)d_in[2];
    const int*   he  = (const int*)d_in[3];
    const int*   eli = (const int*)d_in[4];
    const float* W1  = (const float*)d_in[5];
    const float* b1  = (const float*)d_in[6];
    const float* W2  = (const float*)d_in[7];
    const float* a2s = (const float*)d_in[8];
    const float* a2d = (const float*)d_in[9];
    const float* b2  = (const float*)d_in[10];
    const float* W3  = (const float*)d_in[11];
    const float* a3s = (const float*)d_in[12];
    const float* a3d = (const float*)d_in[13];
    const float* b3  = (const float*)d_in[14];
    const float* Wm1 = (const float*)d_in[15];
    const float* bm1 = (const float*)d_in[16];
    const float* Wm2 = (const float*)d_in[17];
    const float* bm2 = (const float*)d_in[18];
    const float* Wm3 = (const float*)d_in[19];
    const float* bm3 = (const float*)d_in[20];
    const float* Wm4 = (const float*)d_in[21];
    const float* bm4 = (const float*)d_in[22];
    float* out = (float*)d_out;

    void *p_cnt, *p_h0, *p_h1, *p_hg, *p_z, *p_m, *p_as, *p_ad;
    cudaGetSymbolAddress(&p_cnt, c_cnt);
    cudaGetSymbolAddress(&p_h0, g_h0);
    cudaGetSymbolAddress(&p_h1, g_h1);
    cudaGetSymbolAddress(&p_hg, g_hg);
    cudaGetSymbolAddress(&p_z,  g_z);
    cudaGetSymbolAddress(&p_m,  g_m);
    cudaGetSymbolAddress(&p_as, g_as);
    cudaGetSymbolAddress(&p_ad, g_ad);

    const int TB = 256;

    // ===== CSR builds (single memset) =====
    cudaMemsetAsync(p_cnt, 0, sizeof(int) * (N_HE + 2 * N_NODES), 0);
    k_cnt_all<<<cdiv(N_PAIRS + E2, TB), TB>>>(hn, he, ei);
    k_scan3<<<3, 1024>>>();
    k_fill_all<<<cdiv(N_PAIRS + E2, TB), TB>>>(hn, he, ei);

    // ===== hypergraph conv: gather x (128d) -> GEMM on hyperedges -> node gather =====
    k_hc_edge_gather128<<<cdiv(N_HE * 32, TB), TB>>>(x);
    sgemm<128, 128, 16, 8, 8, false, false, false, false><<<dim3(2, cdiv(N_HE, 128)), 256>>>(
        (float*)p_h0, W1, (float*)p_m, N_HE, 256, 128,
        nullptr, nullptr, nullptr, nullptr, nullptr, nullptr, nullptr, nullptr, nullptr);
    k_hc_node_gather<<<cdiv(N_NODES * 2 * 32, TB), TB>>>(b1);

    // ===== GAT layer 1 (256 -> 256) =====
    sgemm<128, 128, 16, 8, 8, false, false, false, false><<<dim3(2, cdiv(N_NODES, 128)), 256>>>(
        (float*)p_h1, W2, (float*)p_hg, N_NODES, 256, 256,
        nullptr, nullptr, nullptr, nullptr, nullptr, nullptr, nullptr, nullptr, nullptr);
    k_dots256<<<cdiv(N_NODES * 32, TB), TB>>>(a2s, a2d);
    k_gat_aggr256<<<cdiv(N_NODES * 2 * 32, TB), TB>>>(b2, (float*)p_h1);

    // ===== GAT layer 2 (256 -> 64), dots fused into GEMM epilogue (no atomics) =====
    sgemm<128, 64, 16, 8, 4, false, false, false, true><<<dim3(1, cdiv(N_NODES, 128)), 256>>>(
        (float*)p_h1, W3, (float*)p_hg, N_NODES, 64, 256,
        nullptr, nullptr, nullptr, nullptr, nullptr,
        a3s, a3d, (float*)p_as, (float*)p_ad);
    k_gat_aggr64<<<cdiv(N_NODES * 32, TB), TB>>>(b3, (float*)p_z);

    // ===== decode MLP as GEMMs (L1 gathers edge features; L3 fuses final+argmax) =====
    float* hA = (float*)p_h1;                       // 100k x 64
    float* hB = (float*)p_h1 + (size_t)L_EDGES * 64;
    sgemm<128, 64, 16, 8, 4, true, true, false, false><<<dim3(1, cdiv(L_EDGES, 128)), 256>>>(
        (float*)p_z, Wm1, hA, L_EDGES, 64, 128,
        bm1, eli, nullptr, nullptr, nullptr, nullptr, nullptr, nullptr, nullptr);
    sgemm<128, 64, 16, 8, 4, true, false, false, false><<<dim3(1, cdiv(L_EDGES, 128)), 256>>>(
        hA, Wm2, hB, L_EDGES, 64, 64,
        bm2, nullptr, nullptr, nullptr, nullptr, nullptr, nullptr, nullptr, nullptr);
    sgemm<128, 64, 16, 8, 4, true, false, true, false><<<dim3(1, cdiv(L_EDGES, 128)), 256>>>(
        hB, Wm3, nullptr, L_EDGES, 64, 64,
        bm3, nullptr, Wm4, bm4, out, nullptr, nullptr, nullptr, nullptr);
}